// round 2
// baseline (speedup 1.0000x reference)
#include <cuda_runtime.h>
#include <math.h>

// Problem constants (fixed by dataset)
#define N_MAX   100000
#define E_MAX   1600000
#define F_INN   512
#define HID     156
#define NCLS    7

// ---------------------------------------------------------------------------
// Scratch (static device globals -- no allocation allowed)
// ---------------------------------------------------------------------------
__device__ __align__(256) float g_h1  [(size_t)N_MAX * HID];   // x @ W1            62.4 MB
__device__ __align__(256) float g_agg1[(size_t)N_MAX * HID];   // aggregated layer1 62.4 MB
__device__ __align__(256) float g_h2  [(size_t)N_MAX * 8];     // relu(.)@W2 (pad8)  3.2 MB
__device__ __align__(256) float g_agg2[(size_t)N_MAX * 8];     // aggregated layer2  3.2 MB
__device__ float g_deg [N_MAX];
__device__ float g_dis [N_MAX];
__device__ float g_norm[E_MAX];

// ---------------------------------------------------------------------------
// Helpers
// ---------------------------------------------------------------------------
static __device__ __forceinline__ unsigned long long fma2(
    unsigned long long a, unsigned long long b, unsigned long long c) {
    unsigned long long d;
    asm("fma.rn.f32x2 %0, %1, %2, %3;" : "=l"(d) : "l"(a), "l"(b), "l"(c));
    return d;
}
static __device__ __forceinline__ unsigned long long dup_f32(float v) {
    unsigned long long u = __float_as_uint(v);
    return u | (u << 32);
}
static __device__ __forceinline__ float lo_f32(unsigned long long u) {
    return __uint_as_float((unsigned)(u & 0xffffffffull));
}
static __device__ __forceinline__ float hi_f32(unsigned long long u) {
    return __uint_as_float((unsigned)(u >> 32));
}
// Vectorized no-return global reduction (REDG.128)
static __device__ __forceinline__ void red_add_v4(float* p, float4 v) {
    asm volatile("red.global.add.v4.f32 [%0], {%1,%2,%3,%4};"
                 :: "l"(p), "f"(v.x), "f"(v.y), "f"(v.z), "f"(v.w) : "memory");
}

// ---------------------------------------------------------------------------
// 1) Degree / normalization precompute
// ---------------------------------------------------------------------------
__global__ void k_init_deg(int n) {
    int i = blockIdx.x * 256 + threadIdx.x;
    if (i < n) g_deg[i] = 1.0f;  // self-loop
}
__global__ void k_count(const int* __restrict__ dst, int e) {
    int i = blockIdx.x * 256 + threadIdx.x;
    if (i < e) atomicAdd(&g_deg[dst[i]], 1.0f);
}
__global__ void k_dis(int n) {
    int i = blockIdx.x * 256 + threadIdx.x;
    if (i < n) g_dis[i] = rsqrtf(g_deg[i]);
}
__global__ void k_norm(const int* __restrict__ src, const int* __restrict__ dst, int e) {
    int i = blockIdx.x * 256 + threadIdx.x;
    if (i < e) g_norm[i] = g_dis[src[i]] * g_dis[dst[i]];
}

// ---------------------------------------------------------------------------
// 2) GEMM1: h1[N,156] = x[N,512] @ W1[512,156]   (packed f32x2 FMA)
//    BM=64, BN=160(156 used), BK=16, 320 threads, micro-tile 8x4 per thread.
//    Epilogue also seeds agg1 = dis^2 * h1 (self-loop term), fusing the old
//    k_selfloop1 pass (saves one 62 MB read of g_h1).
// ---------------------------------------------------------------------------
__global__ __launch_bounds__(320) void k_gemm1(
    const float* __restrict__ x, const float* __restrict__ W1, int n) {
    __shared__ unsigned long long As2[16][64];   // A duplicated (a,a) per elem, 8 KB
    __shared__ unsigned long long Bs [16][80];   // B as float pairs, 10 KB

    const int tid  = threadIdx.x;
    const int m0   = blockIdx.x * 64;
    const int colg = tid % 40;     // 0..39 -> cols [4*colg, 4*colg+3]
    const int rowg = tid / 40;     // 0..7  -> rows [8*rowg, 8*rowg+7]

    unsigned long long acc[8][2];
#pragma unroll
    for (int i = 0; i < 8; i++) { acc[i][0] = 0ull; acc[i][1] = 0ull; }

    float* BsF = (float*)Bs;       // [16][160] view

    for (int kb = 0; kb < F_INN; kb += 16) {
        // --- load A tile (64 rows x 16 k), duplicated into f32x2 lanes ---
        if (tid < 256) {
            int row = tid >> 2;
            int kq  = (tid & 3) * 4;
            int gr  = m0 + row;
            float4 v = make_float4(0.f, 0.f, 0.f, 0.f);
            if (gr < n) v = *(const float4*)&x[(size_t)gr * F_INN + kb + kq];
            As2[kq + 0][row] = dup_f32(v.x);
            As2[kq + 1][row] = dup_f32(v.y);
            As2[kq + 2][row] = dup_f32(v.z);
            As2[kq + 3][row] = dup_f32(v.w);
        }
        // --- load B tile (16 k x 160 cols; cols >=156 zero) ---
#pragma unroll
        for (int j = 0; j < 8; j++) {
            int e = tid + 320 * j;          // 0..2559
            int k = e / 160, c = e % 160;
            BsF[k * 160 + c] = (c < HID) ? W1[(size_t)(kb + k) * HID + c] : 0.0f;
        }
        __syncthreads();

#pragma unroll
        for (int kk = 0; kk < 16; kk++) {
            unsigned long long b0 = Bs[kk][colg * 2];
            unsigned long long b1 = Bs[kk][colg * 2 + 1];
#pragma unroll
            for (int i = 0; i < 8; i++) {
                unsigned long long a = As2[kk][rowg * 8 + i];
                acc[i][0] = fma2(a, b0, acc[i][0]);
                acc[i][1] = fma2(a, b1, acc[i][1]);
            }
        }
        __syncthreads();
    }

    if (colg < 39) {                       // cols 156..159 are padding: skip
        int c0 = colg * 4;
#pragma unroll
        for (int i = 0; i < 8; i++) {
            int r = m0 + rowg * 8 + i;
            if (r < n) {
                float4 o;
                o.x = lo_f32(acc[i][0]); o.y = hi_f32(acc[i][0]);
                o.z = lo_f32(acc[i][1]); o.w = hi_f32(acc[i][1]);
                *(float4*)&g_h1[(size_t)r * HID + c0] = o;
                float d = g_dis[r]; float w = d * d;   // self-loop seed
                float4 s = o;
                s.x *= w; s.y *= w; s.z *= w; s.w *= w;
                *(float4*)&g_agg1[(size_t)r * HID + c0] = s;
            }
        }
    }
}

// ---------------------------------------------------------------------------
// 3) Edge scatter layer 1: agg1[dst] += norm_e * h1[src]   (warp per edge)
// ---------------------------------------------------------------------------
__global__ __launch_bounds__(256) void k_edge1(
    const int* __restrict__ src, const int* __restrict__ dst, int e) {
    int w  = threadIdx.x >> 5;
    int ln = threadIdx.x & 31;
    int ed = blockIdx.x * 8 + w;
    if (ed >= e) return;
    int s = src[ed];            // broadcast loads
    int d = dst[ed];
    float nw = g_norm[ed];
    const float* hr = &g_h1  [(size_t)s * HID];
    float*       ar = &g_agg1[(size_t)d * HID];
#pragma unroll
    for (int j = ln; j < 39; j += 32) {
        float4 v = *(const float4*)&hr[4 * j];
        v.x *= nw; v.y *= nw; v.z *= nw; v.w *= nw;
        red_add_v4(&ar[4 * j], v);
    }
}

// ---------------------------------------------------------------------------
// 4) Layer 2: h2[i] = relu(agg1[i] + b1) @ W2 ; agg2[i] = dis[i]^2 * h2[i]
//    warp per node, W2 (7x156) transposed in smem
// ---------------------------------------------------------------------------
__global__ __launch_bounds__(128) void k_layer2(
    const float* __restrict__ b1, const float* __restrict__ W2, int n) {
    __shared__ float W2s[NCLS][HID];
    for (int idx = threadIdx.x; idx < HID * NCLS; idx += 128) {
        int c = idx / NCLS, k = idx % NCLS;
        W2s[k][c] = W2[(size_t)c * NCLS + k];
    }
    __syncthreads();

    int wid = threadIdx.x >> 5;
    int ln  = threadIdx.x & 31;
    int node = blockIdx.x * 4 + wid;
    if (node >= n) return;

    float acc[NCLS];
#pragma unroll
    for (int k = 0; k < NCLS; k++) acc[k] = 0.f;

#pragma unroll
    for (int q = 0; q < 5; q++) {
        int c = ln + 32 * q;
        if (c < HID) {
            float v = g_agg1[(size_t)node * HID + c] + b1[c];
            v = fmaxf(v, 0.f);
#pragma unroll
            for (int k = 0; k < NCLS; k++) acc[k] = fmaf(v, W2s[k][c], acc[k]);
        }
    }
#pragma unroll
    for (int off = 16; off > 0; off >>= 1) {
#pragma unroll
        for (int k = 0; k < NCLS; k++)
            acc[k] += __shfl_xor_sync(0xffffffffu, acc[k], off);
    }
    if (ln == 0) {
        float d = g_dis[node]; float w = d * d;
        size_t base = (size_t)node * 8;
#pragma unroll
        for (int k = 0; k < NCLS; k++) {
            g_h2  [base + k] = acc[k];
            g_agg2[base + k] = w * acc[k];
        }
        g_h2[base + 7] = 0.f;
        g_agg2[base + 7] = 0.f;
    }
}

// ---------------------------------------------------------------------------
// 5) Edge scatter layer 2: agg2[dst] += norm_e * h2[src]  (thread per edge)
// ---------------------------------------------------------------------------
__global__ __launch_bounds__(256) void k_edge2(
    const int* __restrict__ src, const int* __restrict__ dst, int e) {
    int ed = blockIdx.x * 256 + threadIdx.x;
    if (ed >= e) return;
    int s = src[ed], d = dst[ed];
    float nw = g_norm[ed];
    size_t sb = (size_t)s * 8, db = (size_t)d * 8;
    float4 a = *(const float4*)&g_h2[sb];
    float4 b = *(const float4*)&g_h2[sb + 4];
    a.x *= nw; a.y *= nw; a.z *= nw; a.w *= nw;
    b.x *= nw; b.y *= nw; b.z *= nw; b.w *= nw;  // lane 7 is zero padding
    red_add_v4(&g_agg2[db], a);
    red_add_v4(&g_agg2[db + 4], b);
}

// ---------------------------------------------------------------------------
// 6) Bias + log_softmax
// ---------------------------------------------------------------------------
__global__ void k_finalize(const float* __restrict__ b2, float* __restrict__ out, int n) {
    int i = blockIdx.x * 128 + threadIdx.x;
    if (i >= n) return;
    float v[NCLS];
    size_t base = (size_t)i * 8;
#pragma unroll
    for (int k = 0; k < NCLS; k++) v[k] = g_agg2[base + k] + b2[k];
    float m = v[0];
#pragma unroll
    for (int k = 1; k < NCLS; k++) m = fmaxf(m, v[k]);
    float s = 0.f;
#pragma unroll
    for (int k = 0; k < NCLS; k++) s += expf(v[k] - m);
    float l = m + logf(s);
#pragma unroll
    for (int k = 0; k < NCLS; k++) out[(size_t)i * NCLS + k] = v[k] - l;
}

// ---------------------------------------------------------------------------
// Launch
// ---------------------------------------------------------------------------
extern "C" void kernel_launch(void* const* d_in, const int* in_sizes, int n_in,
                              void* d_out, int out_size) {
    const float* x  = (const float*)d_in[0];
    const int*   ei = (const int*)  d_in[1];
    const float* W1 = (const float*)d_in[2];
    const float* b1 = (const float*)d_in[3];
    const float* W2 = (const float*)d_in[4];
    const float* b2 = (const float*)d_in[5];
    float* out = (float*)d_out;

    const int n = in_sizes[0] / F_INN;   // 100000
    const int e = in_sizes[1] / 2;       // 1600000
    const int* src = ei;
    const int* dst = ei + e;

    // normalization precompute
    k_init_deg<<<(n + 255) / 256, 256>>>(n);
    k_count   <<<(e + 255) / 256, 256>>>(dst, e);
    k_dis     <<<(n + 255) / 256, 256>>>(n);
    k_norm    <<<(e + 255) / 256, 256>>>(src, dst, e);

    // layer 1 (gemm epilogue seeds agg1 with the self-loop term)
    k_gemm1<<<(n + 63) / 64, 320>>>(x, W1, n);
    k_edge1<<<(e + 7) / 8, 256>>>(src, dst, e);

    // layer 2
    k_layer2<<<(n + 3) / 4, 128>>>(b1, W2, n);
    k_edge2<<<(e + 255) / 256, 256>>>(src, dst, e);

    // output
    k_finalize<<<(n + 127) / 128, 128>>>(b2, out, n);
}

// round 4
// speedup vs baseline: 1.5824x; 1.5824x over previous
#include <cuda_runtime.h>
#include <cuda_bf16.h>
#include <math.h>

// Problem constants (fixed by dataset)
#define N_MAX   100000
#define E_MAX   1600000
#define F_INN   512
#define HID     156
#define NCLS    7

// ---------------------------------------------------------------------------
// Scratch (static device globals -- no allocation allowed)
// ---------------------------------------------------------------------------
__device__ __align__(256) float g_h1  [(size_t)N_MAX * HID];   // x @ W1            62.4 MB
__device__ __align__(256) float g_agg1[(size_t)N_MAX * HID];   // aggregated layer1 62.4 MB
__device__ __align__(256) float g_h2  [(size_t)N_MAX * 8];     // relu(.)@W2 (pad8)  3.2 MB
__device__ __align__(256) float g_agg2[(size_t)N_MAX * 8];     // aggregated layer2  3.2 MB
__device__ float g_deg [N_MAX];
__device__ float g_dis [N_MAX];
__device__ float g_norm[E_MAX];
// W1^T, bf16 hi/lo split, pre-arranged in mma B-fragment order:
// [16 kchunks][2 ksteps16][20 n8-tiles][32 lanes][2 regs]  (u32 = bf16x2)
__device__ __align__(256) unsigned g_w1bh[16 * 2 * 20 * 32 * 2];
__device__ __align__(256) unsigned g_w1bl[16 * 2 * 20 * 32 * 2];

// ---------------------------------------------------------------------------
// Helpers
// ---------------------------------------------------------------------------
static __device__ __forceinline__ void red_add_v4(float* p, float4 v) {
    asm volatile("red.global.add.v4.f32 [%0], {%1,%2,%3,%4};"
                 :: "l"(p), "f"(v.x), "f"(v.y), "f"(v.z), "f"(v.w) : "memory");
}
static __device__ __forceinline__ unsigned pack_bf2(float a, float b) {
    __nv_bfloat162 h = __floats2bfloat162_rn(a, b);
    return *(unsigned*)&h;
}
static __device__ __forceinline__ void mma_bf16(
    float* d, const unsigned* a, const unsigned* b) {
    asm volatile(
        "mma.sync.aligned.m16n8k16.row.col.f32.bf16.bf16.f32 "
        "{%0,%1,%2,%3}, {%4,%5,%6,%7}, {%8,%9}, {%0,%1,%2,%3};\n"
        : "+f"(d[0]), "+f"(d[1]), "+f"(d[2]), "+f"(d[3])
        : "r"(a[0]), "r"(a[1]), "r"(a[2]), "r"(a[3]), "r"(b[0]), "r"(b[1]));
}

// ---------------------------------------------------------------------------
// 1) Degree / normalization precompute
// ---------------------------------------------------------------------------
__global__ void k_init_deg(int n) {
    int i = blockIdx.x * 256 + threadIdx.x;
    if (i < n) g_deg[i] = 1.0f;  // self-loop
}
__global__ void k_count(const int* __restrict__ dst, int e) {
    int i = blockIdx.x * 256 + threadIdx.x;
    if (i < e) atomicAdd(&g_deg[dst[i]], 1.0f);
}
__global__ void k_dis(int n) {
    int i = blockIdx.x * 256 + threadIdx.x;
    if (i < n) g_dis[i] = rsqrtf(g_deg[i]);
}
__global__ void k_norm(const int* __restrict__ src, const int* __restrict__ dst, int e) {
    int i = blockIdx.x * 256 + threadIdx.x;
    if (i < e) g_norm[i] = g_dis[src[i]] * g_dis[dst[i]];
}

// ---------------------------------------------------------------------------
// 2a) W1 -> transposed bf16 hi/lo in B-fragment order.
//     Thread per (n, k-pair): n in [0,160), kpair jp in [0,256).
// ---------------------------------------------------------------------------
__global__ void k_w1split(const float* __restrict__ W1) {
    int i = blockIdx.x * 256 + threadIdx.x;
    if (i >= 160 * 256) return;
    int nr = i >> 8;          // 0..159  (n index, cols >=156 are zero pad)
    int jp = i & 255;         // k pair index, k0 = 2*jp
    int k0 = jp * 2;
    float w0 = 0.f, w1 = 0.f;
    if (nr < HID) {
        w0 = W1[(size_t)k0 * HID + nr];
        w1 = W1[(size_t)(k0 + 1) * HID + nr];
    }
    float h0 = __bfloat162float(__float2bfloat16(w0));
    float h1 = __bfloat162float(__float2bfloat16(w1));
    int chunk = jp >> 4;              // k0/32
    int kstep = (jp >> 3) & 1;        // (k0&31)/16
    int j     = jp & 7;               // pair within k16
    int tile  = nr >> 3;
    int t     = (nr & 7) * 4 + (j & 3);
    int reg   = j >> 2;
    int gidx  = ((chunk * 2 + kstep) * 20 + tile) * 64 + t * 2 + reg;
    g_w1bh[gidx] = pack_bf2(h0, h1);
    g_w1bl[gidx] = pack_bf2(w0 - h0, w1 - h1);
}

// ---------------------------------------------------------------------------
// 2b) GEMM1 via mma.sync bf16 (3-term split): h1 = x @ W1, agg1 = dis^2*h1
//     CTA 128x160, 8 warps (warp tile m32 x n80), K chunks of 32,
//     double-buffered smem in fragment order.
// ---------------------------------------------------------------------------
// smem buffer layout (bytes): A_hi 8K | A_lo 8K | B_hi 10K | B_lo 10K = 36K
#define MOF_ALO  8192
#define MOF_BHI  16384
#define MOF_BLO  26624
#define MBUF     36864
#define MSMEM    (2 * MBUF)   // 73728

__global__ __launch_bounds__(256) void k_gemm1_mma(const float* __restrict__ x, int n) {
    extern __shared__ __align__(128) char smarr[];
    const int tid  = threadIdx.x;
    const int wid  = tid >> 5;
    const int lane = tid & 31;
    const int m0   = blockIdx.x * 128;
    const int wm   = wid >> 1;       // 0..3 -> m slices 2wm, 2wm+1
    const int wn   = wid & 1;        // 0..1 -> n8 tiles wn*10 .. +9
    const int sl0  = wm * 2;
    const int tn0  = wn * 10;

    float acc[2][10][4];
#pragma unroll
    for (int s = 0; s < 2; s++)
#pragma unroll
        for (int t = 0; t < 10; t++)
#pragma unroll
            for (int q = 0; q < 4; q++) acc[s][t][q] = 0.f;

    // Prefetch registers
    float4 aR[4];
    uint2  bRh[5], bRl[5];

    // ---- prefetch chunk 0 ----
    {
#pragma unroll
        for (int i = 0; i < 4; i++) {
            int f   = tid + 256 * i;        // float4 index 0..1023
            int row = f >> 3;
            int k0  = (f & 7) * 4;
            int gr  = m0 + row;
            aR[i] = (gr < n) ? *(const float4*)&x[(size_t)gr * F_INN + k0]
                             : make_float4(0.f, 0.f, 0.f, 0.f);
        }
        const uint2* sh = (const uint2*)(g_w1bh);
        const uint2* sl = (const uint2*)(g_w1bl);
#pragma unroll
        for (int i = 0; i < 5; i++) {
            int idx2 = tid + 256 * i;       // uint2 index 0..1279
            bRh[i] = sh[idx2];
            bRl[i] = sl[idx2];
        }
    }

    for (int c = 0; c < 16; c++) {
        char* buf = smarr + (c & 1) * MBUF;
        unsigned* Ah = (unsigned*)buf;
        unsigned* Al = (unsigned*)(buf + MOF_ALO);
        uint2*    Bh = (uint2*)(buf + MOF_BHI);
        uint2*    Bl = (uint2*)(buf + MOF_BLO);

        // ---- store staged chunk c (A: split to hi/lo fragment order) ----
#pragma unroll
        for (int i = 0; i < 4; i++) {
            int f   = tid + 256 * i;
            int row = f >> 3;
            int k0  = (f & 7) * 4;          // k within chunk, multiple of 4
            int slice = row >> 4;
            int kstep = k0 >> 4;
            int j0    = (k0 & 15) >> 1;     // even pair index
            int reg   = ((row >> 3) & 1) + 2 * (j0 >> 2);
            int tA    = (row & 7) * 4 + (j0 & 3);
            int base  = ((slice * 2 + kstep) * 32) * 4;
            float4 v = aR[i];
            float h0 = __bfloat162float(__float2bfloat16(v.x));
            float h1 = __bfloat162float(__float2bfloat16(v.y));
            float h2 = __bfloat162float(__float2bfloat16(v.z));
            float h3 = __bfloat162float(__float2bfloat16(v.w));
            Ah[base + tA * 4 + reg]       = pack_bf2(h0, h1);
            Ah[base + (tA + 1) * 4 + reg] = pack_bf2(h2, h3);
            Al[base + tA * 4 + reg]       = pack_bf2(v.x - h0, v.y - h1);
            Al[base + (tA + 1) * 4 + reg] = pack_bf2(v.z - h2, v.w - h3);
        }
#pragma unroll
        for (int i = 0; i < 5; i++) {
            int idx2 = tid + 256 * i;
            Bh[idx2] = bRh[i];
            Bl[idx2] = bRl[i];
        }
        __syncthreads();

        // ---- prefetch chunk c+1 ----
        if (c < 15) {
            int kc = (c + 1) * 32;
#pragma unroll
            for (int i = 0; i < 4; i++) {
                int f   = tid + 256 * i;
                int row = f >> 3;
                int k0  = (f & 7) * 4;
                int gr  = m0 + row;
                aR[i] = (gr < n) ? *(const float4*)&x[(size_t)gr * F_INN + kc + k0]
                                 : make_float4(0.f, 0.f, 0.f, 0.f);
            }
            const uint2* sh = (const uint2*)(g_w1bh) + (size_t)(c + 1) * 1280;
            const uint2* sl = (const uint2*)(g_w1bl) + (size_t)(c + 1) * 1280;
#pragma unroll
            for (int i = 0; i < 5; i++) {
                int idx2 = tid + 256 * i;
                bRh[i] = sh[idx2];
                bRl[i] = sl[idx2];
            }
        }

        // ---- compute chunk c ----
        const uint4* A4h = (const uint4*)Ah;
        const uint4* A4l = (const uint4*)Al;
#pragma unroll
        for (int ks = 0; ks < 2; ks++) {
            uint4 ah[2], al[2];
#pragma unroll
            for (int s = 0; s < 2; s++) {
                int o = ((sl0 + s) * 2 + ks) * 32 + lane;
                ah[s] = A4h[o];
                al[s] = A4l[o];
            }
            uint2 bh[10], bl[10];
#pragma unroll
            for (int t = 0; t < 10; t++) {
                int o = (ks * 20 + tn0 + t) * 32 + lane;
                bh[t] = Bh[o];
                bl[t] = Bl[o];
            }
#pragma unroll
            for (int s = 0; s < 2; s++) {
#pragma unroll
                for (int t = 0; t < 10; t++) {
                    mma_bf16(acc[s][t], (const unsigned*)&ah[s], (const unsigned*)&bh[t]);
                    mma_bf16(acc[s][t], (const unsigned*)&ah[s], (const unsigned*)&bl[t]);
                    mma_bf16(acc[s][t], (const unsigned*)&al[s], (const unsigned*)&bh[t]);
                }
            }
        }
        __syncthreads();
    }

    // ---- epilogue: write h1 and agg1 = dis^2 * h1 ----
#pragma unroll
    for (int s = 0; s < 2; s++) {
        int rbase = m0 + (sl0 + s) * 16 + (lane >> 2);
#pragma unroll
        for (int half = 0; half < 2; half++) {
            int row = rbase + half * 8;
            if (row < n) {
                float d = g_dis[row];
                float w = d * d;
#pragma unroll
                for (int t = 0; t < 10; t++) {
                    int col = (tn0 + t) * 8 + (lane & 3) * 2;
                    if (col < HID) {
                        float2 v;
                        v.x = acc[s][t][half * 2];
                        v.y = acc[s][t][half * 2 + 1];
                        *(float2*)&g_h1[(size_t)row * HID + col] = v;
                        float2 sv; sv.x = v.x * w; sv.y = v.y * w;
                        *(float2*)&g_agg1[(size_t)row * HID + col] = sv;
                    }
                }
            }
        }
    }
}

// ---------------------------------------------------------------------------
// 3) Edge scatter layer 1: agg1[dst] += norm_e * h1[src]   (warp per edge)
// ---------------------------------------------------------------------------
__global__ __launch_bounds__(256) void k_edge1(
    const int* __restrict__ src, const int* __restrict__ dst, int e) {
    int w  = threadIdx.x >> 5;
    int ln = threadIdx.x & 31;
    int ed = blockIdx.x * 8 + w;
    if (ed >= e) return;
    int s = src[ed];
    int d = dst[ed];
    float nw = g_norm[ed];
    const float* hr = &g_h1  [(size_t)s * HID];
    float*       ar = &g_agg1[(size_t)d * HID];
#pragma unroll
    for (int j = ln; j < 39; j += 32) {
        float4 v = *(const float4*)&hr[4 * j];
        v.x *= nw; v.y *= nw; v.z *= nw; v.w *= nw;
        red_add_v4(&ar[4 * j], v);
    }
}

// ---------------------------------------------------------------------------
// 4) Layer 2: h2[i] = relu(agg1[i] + b1) @ W2 ; agg2[i] = dis[i]^2 * h2[i]
// ---------------------------------------------------------------------------
__global__ __launch_bounds__(128) void k_layer2(
    const float* __restrict__ b1, const float* __restrict__ W2, int n) {
    __shared__ float W2s[NCLS][HID];
    for (int idx = threadIdx.x; idx < HID * NCLS; idx += 128) {
        int c = idx / NCLS, k = idx % NCLS;
        W2s[k][c] = W2[(size_t)c * NCLS + k];
    }
    __syncthreads();

    int wid = threadIdx.x >> 5;
    int ln  = threadIdx.x & 31;
    int node = blockIdx.x * 4 + wid;
    if (node >= n) return;

    float acc[NCLS];
#pragma unroll
    for (int k = 0; k < NCLS; k++) acc[k] = 0.f;

#pragma unroll
    for (int q = 0; q < 5; q++) {
        int c = ln + 32 * q;
        if (c < HID) {
            float v = g_agg1[(size_t)node * HID + c] + b1[c];
            v = fmaxf(v, 0.f);
#pragma unroll
            for (int k = 0; k < NCLS; k++) acc[k] = fmaf(v, W2s[k][c], acc[k]);
        }
    }
#pragma unroll
    for (int off = 16; off > 0; off >>= 1) {
#pragma unroll
        for (int k = 0; k < NCLS; k++)
            acc[k] += __shfl_xor_sync(0xffffffffu, acc[k], off);
    }
    if (ln == 0) {
        float d = g_dis[node]; float w = d * d;
        size_t base = (size_t)node * 8;
#pragma unroll
        for (int k = 0; k < NCLS; k++) {
            g_h2  [base + k] = acc[k];
            g_agg2[base + k] = w * acc[k];
        }
        g_h2[base + 7] = 0.f;
        g_agg2[base + 7] = 0.f;
    }
}

// ---------------------------------------------------------------------------
// 5) Edge scatter layer 2: agg2[dst] += norm_e * h2[src]  (thread per edge)
// ---------------------------------------------------------------------------
__global__ __launch_bounds__(256) void k_edge2(
    const int* __restrict__ src, const int* __restrict__ dst, int e) {
    int ed = blockIdx.x * 256 + threadIdx.x;
    if (ed >= e) return;
    int s = src[ed], d = dst[ed];
    float nw = g_norm[ed];
    size_t sb = (size_t)s * 8, db = (size_t)d * 8;
    float4 a = *(const float4*)&g_h2[sb];
    float4 b = *(const float4*)&g_h2[sb + 4];
    a.x *= nw; a.y *= nw; a.z *= nw; a.w *= nw;
    b.x *= nw; b.y *= nw; b.z *= nw; b.w *= nw;
    red_add_v4(&g_agg2[db], a);
    red_add_v4(&g_agg2[db + 4], b);
}

// ---------------------------------------------------------------------------
// 6) Bias + log_softmax
// ---------------------------------------------------------------------------
__global__ void k_finalize(const float* __restrict__ b2, float* __restrict__ out, int n) {
    int i = blockIdx.x * 128 + threadIdx.x;
    if (i >= n) return;
    float v[NCLS];
    size_t base = (size_t)i * 8;
#pragma unroll
    for (int k = 0; k < NCLS; k++) v[k] = g_agg2[base + k] + b2[k];
    float m = v[0];
#pragma unroll
    for (int k = 1; k < NCLS; k++) m = fmaxf(m, v[k]);
    float s = 0.f;
#pragma unroll
    for (int k = 0; k < NCLS; k++) s += expf(v[k] - m);
    float l = m + logf(s);
#pragma unroll
    for (int k = 0; k < NCLS; k++) out[(size_t)i * NCLS + k] = v[k] - l;
}

// ---------------------------------------------------------------------------
// Launch
// ---------------------------------------------------------------------------
extern "C" void kernel_launch(void* const* d_in, const int* in_sizes, int n_in,
                              void* d_out, int out_size) {
    const float* x  = (const float*)d_in[0];
    const int*   ei = (const int*)  d_in[1];
    const float* W1 = (const float*)d_in[2];
    const float* b1 = (const float*)d_in[3];
    const float* W2 = (const float*)d_in[4];
    const float* b2 = (const float*)d_in[5];
    float* out = (float*)d_out;

    const int n = in_sizes[0] / F_INN;   // 100000
    const int e = in_sizes[1] / 2;       // 1600000
    const int* src = ei;
    const int* dst = ei + e;

    // normalization precompute + W1 split (independent)
    k_init_deg<<<(n + 255) / 256, 256>>>(n);
    k_count   <<<(e + 255) / 256, 256>>>(dst, e);
    k_dis     <<<(n + 255) / 256, 256>>>(n);
    k_norm    <<<(e + 255) / 256, 256>>>(src, dst, e);
    k_w1split <<<160, 256>>>(W1);

    // layer 1: mma.sync bf16 GEMM (epilogue seeds agg1 with the self-loop term)
    static int smem_set = 0;
    if (!smem_set) {
        cudaFuncSetAttribute(k_gemm1_mma, cudaFuncAttributeMaxDynamicSharedMemorySize,
                             MSMEM);
        smem_set = 1;
    }
    k_gemm1_mma<<<(n + 127) / 128, 256, MSMEM>>>(x, n);
    k_edge1<<<(e + 7) / 8, 256>>>(src, dst, e);

    // layer 2
    k_layer2<<<(n + 3) / 4, 128>>>(b1, W2, n);
    k_edge2<<<(e + 255) / 256, 256>>>(src, dst, e);

    // output
    k_finalize<<<(n + 127) / 128, 128>>>(b2, out, n);
}